// round 6
// baseline (speedup 1.0000x reference)
#include <cuda_runtime.h>
#include <cstdint>

#define NN 50000
#define IN_FT 256
#define OUT_FT 64
#define NE 800000
#define NB 196          // scan blocks: 196*256 = 50176 >= NN

// ---------------- device scratch (no allocations allowed) -------------------
__device__ float g_fts[NN * OUT_FT];          // fc(seq) result, 12.8 MB
__device__ int   g_cnt[NN];                   // degree histogram
__device__ int   g_cur[NN];                   // fill cursors
__device__ int   g_off[NN + 256];             // CSR row offsets (padded)
__device__ int   g_bsum[NB];                  // per-block degree sums
__device__ int   g_csrc[NE];                  // CSR edge sources
__device__ float g_cval[NE];                  // CSR edge values

// ---- f32x2 helpers ---------------------------------------------------------
__device__ __forceinline__ void unpack2(unsigned long long v, float& x, float& y) {
    asm("mov.b64 {%0, %1}, %2;" : "=f"(x), "=f"(y) : "l"(v));
}
__device__ __forceinline__ void ffma2(unsigned long long& d,
                                      unsigned long long a, unsigned long long b) {
    asm("fma.rn.f32x2 %0, %1, %2, %3;" : "=l"(d) : "l"(a), "l"(b), "l"(d));
}

// ---------------------------------------------------------------------------
// GEMM: fts[n][o] = sum_k seq[n][k] * W[o][k].
// 128 threads, BM=128, BN=64, BK=16, thread tile 8x8 (8x4 f32x2 acc).
// A stored DUPLICATED in smem: sA[..] holds (a,a) pairs so the FFMA2
// multiplier is a native LDS.64 — no pack MOVs. Layout: 16 ty-groups,
// group stride 296 floats (bank offsets ty*8 -> conflict-free), row
// stride 36 inside group, dup-k at 2*kk.
// B read as native u64 pairs (LDS.64) from sB[k][col], stride 68.
// ---------------------------------------------------------------------------
#define GT 128
#define GRP_S 296
#define ROW_S 36
#define SB_S  68

__global__ __launch_bounds__(GT) void gemm_kernel(
    const float* __restrict__ seq, const float* __restrict__ W,
    float* __restrict__ fts)
{
    __shared__ float sA[16 * GRP_S];                   // 18.5 KB, dup A
    __shared__ __align__(16) float sB[16 * SB_S];      // 4.25 KB

    const int t    = threadIdx.x;
    const int tx   = t & 7;          // cols tx*8 .. tx*8+7
    const int ty   = t >> 3;         // rows ty*8 .. ty*8+7 (group = ty)
    const int row0 = blockIdx.x * 128;

    unsigned long long acc[8][4];
#pragma unroll
    for (int r = 0; r < 8; r++)
#pragma unroll
        for (int c = 0; c < 4; c++) acc[r][c] = 0ull;

    for (int kt = 0; kt < IN_FT; kt += 16) {
        // A tile: 128 rows x 16 k, stored duplicated. 512 float4, 4/thread.
#pragma unroll
        for (int i = 0; i < 4; i++) {
            int idx = t + i * GT;            // 0..511
            int r   = idx >> 2;              // 0..127
            int kq  = idx & 3;               // float4 slot
            float4 v = make_float4(0.f, 0.f, 0.f, 0.f);
            if (row0 + r < NN)
                v = *(const float4*)&seq[(size_t)(row0 + r) * IN_FT + kt + kq * 4];
            float2* p = (float2*)&sA[(r >> 3) * GRP_S + (r & 7) * ROW_S + kq * 8];
            p[0] = make_float2(v.x, v.x);
            p[1] = make_float2(v.y, v.y);
            p[2] = make_float2(v.z, v.z);
            p[3] = make_float2(v.w, v.w);
        }
        // B tile: sB[k][o] = W[o][kt+k]. 256 float4, 2/thread.
#pragma unroll
        for (int i = 0; i < 2; i++) {
            int idx = t + i * GT;
            int o   = idx >> 2;              // 0..63
            int kq  = idx & 3;
            float4 v = *(const float4*)&W[o * IN_FT + kt + kq * 4];
            sB[(kq * 4 + 0) * SB_S + o] = v.x;
            sB[(kq * 4 + 1) * SB_S + o] = v.y;
            sB[(kq * 4 + 2) * SB_S + o] = v.z;
            sB[(kq * 4 + 3) * SB_S + o] = v.w;
        }
        __syncthreads();

        const float* aBase = &sA[ty * GRP_S];
        const float* bBase = &sB[tx * 8];
#pragma unroll
        for (int kk = 0; kk < 16; kk++) {
            const unsigned long long* bp =
                (const unsigned long long*)(bBase + kk * SB_S);
            unsigned long long b0 = bp[0];
            unsigned long long b1 = bp[1];
            unsigned long long b2 = bp[2];
            unsigned long long b3 = bp[3];
#pragma unroll
            for (int r = 0; r < 8; r++) {
                unsigned long long aa =
                    *(const unsigned long long*)(aBase + r * ROW_S + kk * 2);
                ffma2(acc[r][0], aa, b0);
                ffma2(acc[r][1], aa, b1);
                ffma2(acc[r][2], aa, b2);
                ffma2(acc[r][3], aa, b3);
            }
        }
        __syncthreads();
    }

#pragma unroll
    for (int r = 0; r < 8; r++) {
        int row = row0 + ty * 8 + r;
        if (row < NN) {
            float4 v0, v1;
            unpack2(acc[r][0], v0.x, v0.y);
            unpack2(acc[r][1], v0.z, v0.w);
            unpack2(acc[r][2], v1.x, v1.y);
            unpack2(acc[r][3], v1.z, v1.w);
            float* p = &fts[(size_t)row * OUT_FT + tx * 8];
            *(float4*)p       = v0;
            *(float4*)(p + 4) = v1;
        }
    }
}

// ------------------------- CSR build (per call) -----------------------------
__global__ void zero_kernel()
{
    int i = blockIdx.x * blockDim.x + threadIdx.x;
    if (i < NN) { g_cnt[i] = 0; g_cur[i] = 0; }
}

__global__ void hist_kernel(const int* __restrict__ edst)
{
    int e = blockIdx.x * blockDim.x + threadIdx.x;
    if (e < NE) atomicAdd(&g_cnt[edst[e]], 1);
}

__global__ __launch_bounds__(256) void blocksum_kernel()
{
    __shared__ int s[256];
    int t = threadIdx.x;
    int i = blockIdx.x * 256 + t;
    s[t] = (i < NN) ? g_cnt[i] : 0;
    __syncthreads();
#pragma unroll
    for (int d = 128; d > 0; d >>= 1) {
        if (t < d) s[t] += s[t + d];
        __syncthreads();
    }
    if (t == 0) g_bsum[blockIdx.x] = s[0];
}

__global__ __launch_bounds__(256) void scan_kernel()
{
    __shared__ int rb[256];
    __shared__ int s0[256], s1[256];
    int t = threadIdx.x;
    int b = blockIdx.x;

    // base = sum of bsum[0..b-1]
    rb[t] = (t < b && t < NB) ? g_bsum[t] : 0;
    __syncthreads();
#pragma unroll
    for (int d = 128; d > 0; d >>= 1) {
        if (t < d) rb[t] += rb[t + d];
        __syncthreads();
    }
    int base = rb[0];
    __syncthreads();

    int i   = b * 256 + t;
    int val = (i < NN) ? g_cnt[i] : 0;
    s0[t] = val;
    __syncthreads();
    int* src = s0; int* dst = s1;
#pragma unroll
    for (int d = 1; d < 256; d <<= 1) {
        dst[t] = src[t] + ((t >= d) ? src[t - d] : 0);
        __syncthreads();
        int* tmp = src; src = dst; dst = tmp;
    }
    // src[t] = inclusive scan; exclusive = inclusive - val
    if (i <= NN) g_off[i] = base + src[t] - val;
}

__global__ void fill_kernel(const int* __restrict__ esrc,
                            const int* __restrict__ edst,
                            const float* __restrict__ eval)
{
    int e = blockIdx.x * blockDim.x + threadIdx.x;
    if (e < NE) {
        int d = edst[e];
        int p = g_off[d] + atomicAdd(&g_cur[d], 1);
        g_csrc[p] = esrc[e];
        g_cval[p] = eval[e];
    }
}

// ---------------------------------------------------------------------------
// Gather: out[d] = prelu(sum_{e in bin d} fts[src[e]] * val[e] + bias).
// Atomic-free: writes each output element exactly once. 16 lanes per row
// (one float4 chunk each), 16 rows per 256-thread block. 2-way unrolled
// edge loop for MLP.
// ---------------------------------------------------------------------------
__global__ __launch_bounds__(256) void gather_kernel(
    const float4* __restrict__ fts4,
    const float* __restrict__ bias, const float* __restrict__ alpha,
    float4* __restrict__ out4)
{
    int t = threadIdx.x;
    int d = blockIdx.x * 16 + (t >> 4);
    int j = t & 15;
    if (d >= NN) return;

    int e   = g_off[d];
    int end = g_off[d + 1];

    float4 a0 = make_float4(0.f, 0.f, 0.f, 0.f);
    float4 a1 = make_float4(0.f, 0.f, 0.f, 0.f);
    for (; e + 1 < end; e += 2) {
        int   s0 = g_csrc[e],     s1 = g_csrc[e + 1];
        float v0 = g_cval[e],     v1 = g_cval[e + 1];
        float4 f0 = fts4[(size_t)s0 * 16 + j];
        float4 f1 = fts4[(size_t)s1 * 16 + j];
        a0.x += f0.x * v0; a0.y += f0.y * v0; a0.z += f0.z * v0; a0.w += f0.w * v0;
        a1.x += f1.x * v1; a1.y += f1.y * v1; a1.z += f1.z * v1; a1.w += f1.w * v1;
    }
    if (e < end) {
        int   s0 = g_csrc[e];
        float v0 = g_cval[e];
        float4 f0 = fts4[(size_t)s0 * 16 + j];
        a0.x += f0.x * v0; a0.y += f0.y * v0; a0.z += f0.z * v0; a0.w += f0.w * v0;
    }

    float4 bb = ((const float4*)bias)[j];
    float  al = __ldg(&alpha[0]);
    float4 r;
    r.x = a0.x + a1.x + bb.x;
    r.y = a0.y + a1.y + bb.y;
    r.z = a0.z + a1.z + bb.z;
    r.w = a0.w + a1.w + bb.w;
    r.x = (r.x >= 0.f) ? r.x : al * r.x;
    r.y = (r.y >= 0.f) ? r.y : al * r.y;
    r.z = (r.z >= 0.f) ? r.z : al * r.z;
    r.w = (r.w >= 0.f) ? r.w : al * r.w;
    out4[(size_t)d * 16 + j] = r;
}

extern "C" void kernel_launch(void* const* d_in, const int* in_sizes, int n_in,
                              void* d_out, int out_size)
{
    const float* seq   = (const float*)d_in[0];
    const float* W     = (const float*)d_in[1];
    const float* bias  = (const float*)d_in[2];
    const float* alpha = (const float*)d_in[3];
    const int*   esrc  = (const int*)d_in[4];
    const int*   edst  = (const int*)d_in[5];
    const float* eval  = (const float*)d_in[6];
    float* out = (float*)d_out;

    float* fts;
    cudaGetSymbolAddress((void**)&fts, g_fts);

    // CSR build
    zero_kernel<<<(NN + 255) / 256, 256>>>();
    hist_kernel<<<(NE + 255) / 256, 256>>>(edst);
    blocksum_kernel<<<NB, 256>>>();
    scan_kernel<<<NB, 256>>>();
    fill_kernel<<<(NE + 255) / 256, 256>>>(esrc, edst, eval);

    // GEMM: fts = seq @ W^T
    gemm_kernel<<<(NN + 127) / 128, GT>>>(seq, W, fts);

    // Gather + bias + PReLU (single write per output element)
    gather_kernel<<<(NN + 15) / 16, 256>>>((const float4*)fts, bias, alpha,
                                           (float4*)out);
}